// round 13
// baseline (speedup 1.0000x reference)
#include <cuda_runtime.h>
#include <math.h>

#define BATCH 2048
#define XF    1024
#define XF4   (XF / 4)
#define G     16

#define CH    32                // row chunks (64 rows each)
#define RPCH  (BATCH / CH)      // 64 rows per chunk
#define RPT   8                 // rows per thread inside a chunk
#define NBLK  256               // kA grid (8 col-groups x 32 chunks)

// Scratch (allocation-free: __device__ globals)
__device__ float g_p0[CH * XF];
__device__ float g_p1[CH * XF];
__device__ float g_p2[CH * XF];
__device__ float g_mean[XF];

__device__ unsigned g_count = 0;
__device__ unsigned g_gen   = 0;   // monotone generation (replay-safe)

__device__ __forceinline__ void grid_barrier() {
    __syncthreads();
    if (threadIdx.x == 0) {
        volatile unsigned* genp = (volatile unsigned*)&g_gen;
        unsigned gen = *genp;
        __threadfence();                   // publish this block's stores
        if (atomicAdd(&g_count, 1u) == NBLK - 1u) {
            g_count = 0;                   // safe: no re-arrival until gen bumps
            __threadfence();
            *genp = gen + 1u;              // release
        } else {
            while (*genp == gen) { }       // read-only spin
        }
        __threadfence();                   // acquire
    }
    __syncthreads();
}

// ---------------------------------------------------------------------------
// Kernel A: phase 1 (R7 k1 body) + grid barrier + phase 2 (R7 k2 body).
// grid = 256: b&7 = 128-col group, b>>3 = 64-row chunk. 2 blocks/SM -> all
// 256 co-resident (296 slots), barrier deadlock-free.
__global__ __launch_bounds__(256, 2)
void kA_stats(const float* __restrict__ xf) {
    __shared__ float4 sh[8][32];
    __shared__ float4 shm[32];
    const int c4 = threadIdx.x & 31, rg = threadIdx.x >> 5;
    const int cg = blockIdx.x & 7, chunk = blockIdx.x >> 3;
    const int col4 = cg * 32 + c4;
    const int row0 = chunk * RPCH + rg * RPT;

    // ---- Phase 1: per-chunk column sums ----
    {
        const float4* p = (const float4*)xf + (size_t)row0 * XF4 + col4;
        float4 s = make_float4(0.f, 0.f, 0.f, 0.f);
#pragma unroll
        for (int r = 0; r < RPT; r++) {
            float4 x = p[(size_t)r * XF4];
            s.x += x.x; s.y += x.y; s.z += x.z; s.w += x.w;
        }
        sh[rg][c4] = s;
        __syncthreads();
        if (rg == 0) {
            float4 t = sh[0][c4];
#pragma unroll
            for (int i = 1; i < 8; i++) {
                float4 u = sh[i][c4];
                t.x += u.x; t.y += u.y; t.z += u.z; t.w += u.w;
            }
            ((float4*)(g_p0 + chunk * XF))[col4] = t;
        }
    }
    grid_barrier();

    // ---- Phase 2: fold 32 mean-partials in-block, then stats partials ----
    {
        float4 s = make_float4(0.f, 0.f, 0.f, 0.f);
#pragma unroll
        for (int i = 0; i < 4; i++) {          // rg folds chunks rg*4..rg*4+3
            float4 u = ((const float4*)(g_p0 + (rg * 4 + i) * XF))[col4];
            s.x += u.x; s.y += u.y; s.z += u.z; s.w += u.w;
        }
        sh[rg][c4] = s;
        __syncthreads();
        if (rg == 0) {
            float4 t = sh[0][c4];
#pragma unroll
            for (int i = 1; i < 8; i++) {
                float4 u = sh[i][c4];
                t.x += u.x; t.y += u.y; t.z += u.z; t.w += u.w;
            }
            const float inv = 1.0f / BATCH;
            t.x *= inv; t.y *= inv; t.z *= inv; t.w *= inv;
            shm[c4] = t;
            if (chunk == 0) ((float4*)g_mean)[col4] = t;
        }
        __syncthreads();
        float4 m = shm[c4];

        const float4* p = (const float4*)xf + (size_t)row0 * XF4 + col4;
        float4 s1 = make_float4(0.f, 0.f, 0.f, 0.f);
        float4 s2 = make_float4(0.f, 0.f, 0.f, 0.f);
#pragma unroll
        for (int r = 0; r < RPT; r++) {
            float4 x = p[(size_t)r * XF4];
            float vx = fmaxf(x.x - m.x, 0.f);
            float vy = fmaxf(x.y - m.y, 0.f);
            float vz = fmaxf(x.z - m.z, 0.f);
            float vw = fmaxf(x.w - m.w, 0.f);
            s1.x += vx; s1.y += vy; s1.z += vz; s1.w += vw;
            s2.x += vx * vx; s2.y += vy * vy; s2.z += vz * vz; s2.w += vw * vw;
        }
        __syncthreads();
        sh[rg][c4] = s1;
        __syncthreads();
        if (rg == 0) {
            float4 t = sh[0][c4];
#pragma unroll
            for (int i = 1; i < 8; i++) {
                float4 u = sh[i][c4];
                t.x += u.x; t.y += u.y; t.z += u.z; t.w += u.w;
            }
            ((float4*)(g_p1 + chunk * XF))[col4] = t;
        }
        __syncthreads();
        sh[rg][c4] = s2;
        __syncthreads();
        if (rg == 0) {
            float4 t = sh[0][c4];
#pragma unroll
            for (int i = 1; i < 8; i++) {
                float4 u = sh[i][c4];
                t.x += u.x; t.y += u.y; t.z += u.z; t.w += u.w;
            }
            ((float4*)(g_p2 + chunk * XF))[col4] = t;
        }
    }
}

// ---------------------------------------------------------------------------
// Kernel B: R7 k3, byte-identical. Fold 32 stats-partials for this 64-col
// tile -> (a,b); write 16-way tiled output with streaming stores.
// grid=(16,16): bx = 64-col tile, by = 128-row tile. block=256.
#define COLS_B 64
#define ROWS_B 128
__global__ __launch_bounds__(256) void kB_out(const float* __restrict__ xf,
                                              const float* __restrict__ wp,
                                              float* __restrict__ out) {
    __shared__ float sh1[4][COLS_B], sh2[4][COLS_B];
    __shared__ float s_m[COLS_B], s_a[COLS_B], s_b[COLS_B];
    int tid = threadIdx.x;
    int col0 = blockIdx.x * COLS_B;

    {   // fold: cc = col, gg folds 8 chunks each
        int cc = tid & 63, gg = tid >> 6;
        int col = col0 + cc;
        float s1 = 0.f, s2 = 0.f;
#pragma unroll
        for (int i = 0; i < 8; i++) {
            int idx = (gg * 8 + i) * XF + col;
            s1 += g_p1[idx];
            s2 += g_p2[idx];
        }
        sh1[gg][cc] = s1;
        sh2[gg][cc] = s2;
    }
    __syncthreads();
    if (tid < COLS_B) {
        float s1 = sh1[0][tid] + sh1[1][tid] + sh1[2][tid] + sh1[3][tid];
        float s2 = sh2[0][tid] + sh2[1][tid] + sh2[2][tid] + sh2[3][tid];
        float mu  = s1 * (1.0f / BATCH);
        float var = (s2 - (float)BATCH * mu * mu) * (1.0f / (BATCH - 1));
        float a   = wp[0] * rsqrtf(var);
        s_m[tid] = g_mean[col0 + tid];
        s_a[tid] = a;
        s_b[tid] = -a * mu;
    }
    __syncthreads();

    int cidx = tid & 15;
    int ridx = tid >> 4;
    int col  = col0 + cidx * 4;

    float4 m = *(const float4*)(s_m + cidx * 4);
    float4 a = *(const float4*)(s_a + cidx * 4);
    float4 b = *(const float4*)(s_b + cidx * 4);

#pragma unroll
    for (int j = 0; j < ROWS_B / 16; j++) {     // 8 rows per thread
        int row = blockIdx.y * ROWS_B + ridx + j * 16;
        float4 x = *(const float4*)(xf + (size_t)row * XF + col);
        float4 v;
        v.x = fmaxf(x.x - m.x, 0.f) * a.x + b.x;
        v.y = fmaxf(x.y - m.y, 0.f) * a.y + b.y;
        v.z = fmaxf(x.z - m.z, 0.f) * a.z + b.z;
        v.w = fmaxf(x.w - m.w, 0.f) * a.w + b.w;

        float* orow = out + (size_t)row * (G * XF) + col;
#pragma unroll
        for (int k = 0; k < G; k++)
            __stcs((float4*)(orow + (size_t)k * XF), v);
    }
}

extern "C" void kernel_launch(void* const* d_in, const int* in_sizes, int n_in,
                              void* d_out, int out_size) {
    const float* xf = (const float*)d_in[0];
    const float* wp = (const float*)d_in[1];
    float* out = (float*)d_out;

    kA_stats<<<NBLK, 256>>>(xf);
    kB_out<<<dim3(XF / COLS_B, BATCH / ROWS_B), 256>>>(xf, wp, out);
}

// round 15
// speedup vs baseline: 1.4148x; 1.4148x over previous
#include <cuda_runtime.h>
#include <math.h>

#define BATCH 2048
#define XF    1024
#define XF4   (XF / 4)
#define G     16

// Scratch (allocation-free: __device__ globals)
__device__ float g_mean[XF];
__device__ float g_a[XF];
__device__ float g_b[XF];

// ---------------------------------------------------------------------------
// kS: full column statistics in ONE kernel, block-local syncs only.
// grid = 64 blocks; block b owns columns [b*16, b*16+16) (4 float4 lanes).
// Thread layout: c4 = tid&3 (float4 lane), rg = tid>>2 (64 row-groups x 32).
// Pass 1: batch mean of its 16 columns. Pass 2: relu stats -> a, b.
__global__ __launch_bounds__(256) void kS_stats(const float* __restrict__ xf,
                                                const float* __restrict__ wp) {
    __shared__ float4 shA[64][4];
    __shared__ float4 shB[64][4];
    __shared__ float4 shm[4];

    const int tid = threadIdx.x;
    const int c4 = tid & 3, rg = tid >> 2;
    const int col4 = blockIdx.x * 4 + c4;
    const float4* p = (const float4*)xf + (size_t)(rg * 32) * XF4 + col4;

    // ---- Pass 1: column sums over 32 rows per thread ----
    {
        float4 s = make_float4(0.f, 0.f, 0.f, 0.f);
#pragma unroll 8
        for (int r = 0; r < 32; r++) {
            float4 x = p[(size_t)r * XF4];
            s.x += x.x; s.y += x.y; s.z += x.z; s.w += x.w;
        }
        shA[rg][c4] = s;
    }
    __syncthreads();
    if (rg < 8) {                       // fold 64 groups -> 8
        float4 t = shA[rg][c4];
#pragma unroll
        for (int i = 1; i < 8; i++) {
            float4 u = shA[rg + 8 * i][c4];
            t.x += u.x; t.y += u.y; t.z += u.z; t.w += u.w;
        }
        shB[rg][c4] = t;
    }
    __syncthreads();
    if (tid < 4) {                      // fold 8 -> 1, mean
        float4 t = shB[0][tid];
#pragma unroll
        for (int i = 1; i < 8; i++) {
            float4 u = shB[i][tid];
            t.x += u.x; t.y += u.y; t.z += u.z; t.w += u.w;
        }
        const float inv = 1.0f / BATCH;
        t.x *= inv; t.y *= inv; t.z *= inv; t.w *= inv;
        shm[tid] = t;
        ((float4*)g_mean)[blockIdx.x * 4 + tid] = t;
    }
    __syncthreads();
    float4 m = shm[c4];

    // ---- Pass 2: sum / sumsq of relu(x - m) (xf now L2-hot) ----
    {
        float4 s1 = make_float4(0.f, 0.f, 0.f, 0.f);
        float4 s2 = make_float4(0.f, 0.f, 0.f, 0.f);
#pragma unroll 8
        for (int r = 0; r < 32; r++) {
            float4 x = p[(size_t)r * XF4];
            float vx = fmaxf(x.x - m.x, 0.f);
            float vy = fmaxf(x.y - m.y, 0.f);
            float vz = fmaxf(x.z - m.z, 0.f);
            float vw = fmaxf(x.w - m.w, 0.f);
            s1.x += vx; s1.y += vy; s1.z += vz; s1.w += vw;
            s2.x += vx * vx; s2.y += vy * vy; s2.z += vz * vz; s2.w += vw * vw;
        }
        shA[rg][c4] = s1;
        shB[rg][c4] = s2;
    }
    __syncthreads();
    if (rg < 8) {                       // fold 64 -> 8 (both arrays)
        float4 t1 = shA[rg][c4], t2 = shB[rg][c4];
#pragma unroll
        for (int i = 1; i < 8; i++) {
            float4 u1 = shA[rg + 8 * i][c4], u2 = shB[rg + 8 * i][c4];
            t1.x += u1.x; t1.y += u1.y; t1.z += u1.z; t1.w += u1.w;
            t2.x += u2.x; t2.y += u2.y; t2.z += u2.z; t2.w += u2.w;
        }
        __syncthreads();                // all reads done before overwrite
        shA[rg][c4] = t1;
        shB[rg][c4] = t2;
    } else {
        __syncthreads();
    }
    __syncthreads();
    if (tid < 4) {                      // fold 8 -> 1, compute a, b
        float4 s1 = shA[0][tid], s2 = shB[0][tid];
#pragma unroll
        for (int i = 1; i < 8; i++) {
            float4 u1 = shA[i][tid], u2 = shB[i][tid];
            s1.x += u1.x; s1.y += u1.y; s1.z += u1.z; s1.w += u1.w;
            s2.x += u2.x; s2.y += u2.y; s2.z += u2.z; s2.w += u2.w;
        }
        const float invN = 1.0f / BATCH;
        const float invV = 1.0f / (BATCH - 1);
        float w = wp[0];
        float4 mu, a, b;
        mu.x = s1.x * invN; mu.y = s1.y * invN;
        mu.z = s1.z * invN; mu.w = s1.w * invN;
        a.x = w * rsqrtf((s2.x - (float)BATCH * mu.x * mu.x) * invV);
        a.y = w * rsqrtf((s2.y - (float)BATCH * mu.y * mu.y) * invV);
        a.z = w * rsqrtf((s2.z - (float)BATCH * mu.z * mu.z) * invV);
        a.w = w * rsqrtf((s2.w - (float)BATCH * mu.w * mu.w) * invV);
        b.x = -a.x * mu.x; b.y = -a.y * mu.y;
        b.z = -a.z * mu.z; b.w = -a.w * mu.w;
        ((float4*)g_a)[blockIdx.x * 4 + tid] = a;
        ((float4*)g_b)[blockIdx.x * 4 + tid] = b;
    }
}

// ---------------------------------------------------------------------------
// kB: R7 output kernel; prologue is now direct m,a,b loads (no fold).
// grid=(16,16): bx = 64-col tile, by = 128-row tile. block=256. __stcs.
#define COLS_B 64
#define ROWS_B 128
__global__ __launch_bounds__(256) void kB_out(const float* __restrict__ xf,
                                              float* __restrict__ out) {
    __shared__ float s_m[COLS_B], s_a[COLS_B], s_b[COLS_B];
    int tid = threadIdx.x;
    int col0 = blockIdx.x * COLS_B;

    if (tid < COLS_B) {
        s_m[tid] = g_mean[col0 + tid];
        s_a[tid] = g_a[col0 + tid];
        s_b[tid] = g_b[col0 + tid];
    }
    __syncthreads();

    int cidx = tid & 15;          // float4 within the 64-col tile
    int ridx = tid >> 4;          // 0..15
    int col  = col0 + cidx * 4;

    float4 m = *(const float4*)(s_m + cidx * 4);
    float4 a = *(const float4*)(s_a + cidx * 4);
    float4 b = *(const float4*)(s_b + cidx * 4);

#pragma unroll
    for (int j = 0; j < ROWS_B / 16; j++) {     // 8 rows per thread
        int row = blockIdx.y * ROWS_B + ridx + j * 16;
        float4 x = *(const float4*)(xf + (size_t)row * XF + col);
        float4 v;
        v.x = fmaxf(x.x - m.x, 0.f) * a.x + b.x;
        v.y = fmaxf(x.y - m.y, 0.f) * a.y + b.y;
        v.z = fmaxf(x.z - m.z, 0.f) * a.z + b.z;
        v.w = fmaxf(x.w - m.w, 0.f) * a.w + b.w;

        float* orow = out + (size_t)row * (G * XF) + col;
#pragma unroll
        for (int k = 0; k < G; k++)
            __stcs((float4*)(orow + (size_t)k * XF), v);
    }
}

extern "C" void kernel_launch(void* const* d_in, const int* in_sizes, int n_in,
                              void* d_out, int out_size) {
    const float* xf = (const float*)d_in[0];
    const float* wp = (const float*)d_in[1];
    float* out = (float*)d_out;

    kS_stats<<<XF / 16, 256>>>(xf, wp);
    kB_out<<<dim3(XF / COLS_B, BATCH / ROWS_B), 256>>>(xf, out);
}